// round 2
// baseline (speedup 1.0000x reference)
#include <cuda_runtime.h>
#include <math_constants.h>
#include <cstdint>

// FLoss: weighted BCE, weights = W / (dist_to_argmax_centroid + 1)
// input  d_in[0]: [B,1,T,W,W] f32  (same linear layout as [B,T,W,W])
// target d_in[1]: [B,T,W,W]   f32
// out: scalar f32 = -mean(w * (t*clip(log p,-100) + (1-t)*clip(log1p(-p),-100)))

#define WDIM 256
#define FRAME_ELEMS (WDIM * WDIM)          // 65536
#define FRAME_ELEMS4 (FRAME_ELEMS / 4)     // 16384
#define MAX_FRAMES 4096

__device__ float  g_cx[MAX_FRAMES];   // mean row index of argmax pixels
__device__ float  g_cy[MAX_FRAMES];   // mean col index
__device__ double g_acc;

// ---------------------------------------------------------------------------
// Kernel 1: per-frame max + centroid of maximal pixels, single pass.
// One CTA (1024 threads) per frame; 16x float4 per thread.
// Running-max trick: each thread keeps (lmax, cnt, sum_row, sum_col) of pixels
// equal to its local max; after the block max is known, only threads whose
// lmax == gmax contribute their payloads (exact float equality semantics,
// identical to the reference's target == max mask).
// ---------------------------------------------------------------------------
__global__ __launch_bounds__(1024) void frame_stats_kernel(const float* __restrict__ tgt)
{
    const int f   = blockIdx.x;
    const int tid = threadIdx.x;
    const float4* base = reinterpret_cast<const float4*>(tgt) + (size_t)f * FRAME_ELEMS4;

    float lmax = -CUDART_INF_F;
    float sx = 0.f, sy = 0.f, cnt = 0.f;

    #pragma unroll
    for (int k = 0; k < 16; k++) {
        const int e4 = tid + k * 1024;
        const float4 v = __ldg(base + e4);
        const int e = e4 * 4;                      // 4 consecutive elems, same row
        const float row  = (float)(e >> 8);
        const float col0 = (float)(e & 255);
        const float vals[4] = {v.x, v.y, v.z, v.w};
        #pragma unroll
        for (int c = 0; c < 4; c++) {
            const float val = vals[c];
            const float col = col0 + (float)c;
            if (val > lmax)       { lmax = val; cnt = 1.f; sx = row; sy = col; }
            else if (val == lmax) { cnt += 1.f; sx += row; sy += col; }
        }
    }

    // block max reduction
    __shared__ float s_wmax[32];
    __shared__ float s_gmax;
    __shared__ float s_sx, s_sy, s_cnt;

    float wm = lmax;
    #pragma unroll
    for (int o = 16; o; o >>= 1) wm = fmaxf(wm, __shfl_xor_sync(0xffffffffu, wm, o));
    if ((tid & 31) == 0) s_wmax[tid >> 5] = wm;
    if (tid == 0) { s_sx = 0.f; s_sy = 0.f; s_cnt = 0.f; }
    __syncthreads();
    if (tid < 32) {
        float m = s_wmax[tid];
        #pragma unroll
        for (int o = 16; o; o >>= 1) m = fmaxf(m, __shfl_xor_sync(0xffffffffu, m, o));
        if (tid == 0) s_gmax = m;
    }
    __syncthreads();

    if (lmax == s_gmax) {
        atomicAdd(&s_cnt, cnt);
        atomicAdd(&s_sx,  sx);
        atomicAdd(&s_sy,  sy);
    }
    __syncthreads();

    if (tid == 0) {
        g_cx[f] = s_sx / s_cnt;
        g_cy[f] = s_sy / s_cnt;
        if (f == 0) g_acc = 0.0;   // reset accumulator each replay (runs before loss kernel)
    }
}

// ---------------------------------------------------------------------------
// Kernel 2: weighted BCE accumulation, grid-stride over float4 pairs.
// Per element: 2x LG2, 1x SQRT.approx, 1x RCP (via __fdividef).
// ---------------------------------------------------------------------------
__global__ __launch_bounds__(256) void loss_kernel(const float* __restrict__ inp,
                                                   const float* __restrict__ tgt,
                                                   int total4)
{
    __shared__ double s_acc;
    if (threadIdx.x == 0) s_acc = 0.0;
    __syncthreads();

    const float4* P = reinterpret_cast<const float4*>(inp);
    const float4* T = reinterpret_cast<const float4*>(tgt);

    float lsum = 0.f;
    const int stride = gridDim.x * blockDim.x;
    for (int i = blockIdx.x * blockDim.x + threadIdx.x; i < total4; i += stride) {
        const int f = i >> 14;                         // frame index (16384 float4 / frame)
        const float cx = __ldg(&g_cx[f]);
        const float cy = __ldg(&g_cy[f]);

        const int e = i * 4;
        const float row  = (float)((e >> 8) & 255);
        const float col0 = (float)(e & 255);

        const float4 p4 = __ldg(P + i);
        const float4 t4 = __ldg(T + i);

        const float di  = row - cx;
        const float di2 = di * di;

        const float pv[4] = {p4.x, p4.y, p4.z, p4.w};
        const float tv[4] = {t4.x, t4.y, t4.z, t4.w};

        #pragma unroll
        for (int c = 0; c < 4; c++) {
            const float dj = (col0 + (float)c) - cy;
            const float s  = fmaf(dj, dj, di2);
            float dist;
            asm("sqrt.approx.f32 %0, %1;" : "=f"(dist) : "f"(s));   // sqrt.approx(0)=0
            const float wgt = __fdividef(256.0f, dist + 1.0f);

            const float p = pv[c];
            const float t = tv[c];
            const float lp = fmaxf(__logf(p),        -100.0f);
            const float lq = fmaxf(__logf(1.0f - p), -100.0f);
            // t*lp + (1-t)*lq = lq + t*(lp - lq)
            const float term = fmaf(t, lp - lq, lq);
            lsum = fmaf(wgt, term, lsum);
        }
    }

    // warp reduce -> smem double -> global double
    #pragma unroll
    for (int o = 16; o; o >>= 1) lsum += __shfl_xor_sync(0xffffffffu, lsum, o);
    if ((threadIdx.x & 31) == 0) atomicAdd(&s_acc, (double)lsum);
    __syncthreads();
    if (threadIdx.x == 0) atomicAdd(&g_acc, s_acc);
}

// ---------------------------------------------------------------------------
// Kernel 3: finalize
// ---------------------------------------------------------------------------
__global__ void finalize_kernel(float* __restrict__ out, double inv_n)
{
    out[0] = (float)(-g_acc * inv_n);
}

extern "C" void kernel_launch(void* const* d_in, const int* in_sizes, int n_in,
                              void* d_out, int out_size)
{
    const float* inp = (const float*)d_in[0];
    const float* tgt = (const float*)d_in[1];
    float* out = (float*)d_out;

    const int n       = in_sizes[1];       // B*T*W*W
    const int nframes = n >> 16;           // / 65536
    const int total4  = n >> 2;

    frame_stats_kernel<<<nframes, 1024>>>(tgt);

    const int grid = 148 * 16;             // grid-stride; ~7 float4 iters/thread
    loss_kernel<<<grid, 256>>>(inp, tgt, total4);

    finalize_kernel<<<1, 1>>>(out, 1.0 / (double)n);
}